// round 5
// baseline (speedup 1.0000x reference)
#include <cuda_runtime.h>
#include <cuda_bf16.h>

#define NSAMPLE 32
#define NPTS 4096
#define BLOCK_THREADS 256
#define WARPS_PER_BLOCK (BLOCK_THREADS / 32)

// One warp per query point, sources read from global memory (48KB/batch ->
// L1/L2 resident). Each iteration the warp tests 32 consecutive source
// indices; __ballot_sync yields hits in ascending-index order; popc-prefix
// ranks map hits to output slots; warp-uniform break at 32 hits; remaining
// slots padded with the smallest hit index (self-hit guarantees it exists).
//
// OUTPUT IS WRITTEN AS float32: the harness compares against the reference
// cast to the __output__ dtype, and norm-based rel_err == exactly 1.0 across
// all prior rounds is the signature of int32 index bits being reinterpreted
// as (denormal ~ 0) floats. Indices <= 4095 are exactly representable in f32.
__global__ void ball_query_kernel(const float* __restrict__ xyz,
                                  float* __restrict__ out) {
    const int lane = threadIdx.x & 31;
    const int gw = blockIdx.x * WARPS_PER_BLOCK + (threadIdx.x >> 5);
    const int b = gw >> 12;          // / NPTS
    const int m = gw & (NPTS - 1);   // % NPTS

    const float* src = xyz + (size_t)b * NPTS * 3;

    const float qx = src[m * 3 + 0];
    const float qy = src[m * 3 + 1];
    const float qz = src[m * 3 + 2];
    // |q|^2 with the reference's exact order ((x*x + y*y) + z*z); rn
    // intrinsics block FMA contraction so thresholding is bit-exact.
    const float qw = __fadd_rn(__fadd_rn(__fmul_rn(qx, qx), __fmul_rn(qy, qy)),
                               __fmul_rn(qz, qz));

    float* o = out + (size_t)gw * NSAMPLE;

    int count = 0;
    int first = -1;
    const float r2 = 0.04f;  // f32 promotion of 0.2*0.2, as jnp compares

    for (int nb = 0; nb < NPTS; nb += 32) {
        const int n = nb + lane;
        const float px = src[n * 3 + 0];
        const float py = src[n * 3 + 1];
        const float pz = src[n * 3 + 2];
        const float pw = __fadd_rn(__fadd_rn(__fmul_rn(px, px), __fmul_rn(py, py)),
                                   __fmul_rn(pz, pz));
        const float dot = __fadd_rn(__fadd_rn(__fmul_rn(qx, px), __fmul_rn(qy, py)),
                                    __fmul_rn(qz, pz));
        // d2 = (|q|^2 + |p|^2) - 2*dot, exact reference expression order.
        const float d2 = __fadd_rn(__fadd_rn(qw, pw), -__fmul_rn(2.0f, dot));

        const bool hit = d2 < r2;
        const unsigned bal = __ballot_sync(0xffffffffu, hit);
        if (bal) {
            if (first < 0) first = nb + (__ffs(bal) - 1);
            const int rank = __popc(bal & ((1u << lane) - 1u));
            if (hit) {
                const int slot = count + rank;
                if (slot < NSAMPLE) o[slot] = (float)n;
            }
            count += __popc(bal);
            if (count >= NSAMPLE) break;  // count is warp-uniform
        }
    }

    if (count < NSAMPLE) {
        const int i = count + lane;
        if (i < NSAMPLE) o[i] = (float)first;
    }
}

extern "C" void kernel_launch(void* const* d_in, const int* in_sizes, int n_in,
                              void* d_out, int out_size) {
    const float* xyz = (const float*)d_in[0];  // 'xyz' (B, N, 3) float32
    // d_in[1] ('xyz_new') is unused by the reference (it queries xyz vs xyz).
    const int B = in_sizes[0] / (NPTS * 3);    // 8
    float* out = (float*)d_out;

    const int total_warps = B * NPTS;                  // 32768
    const int blocks = total_warps / WARPS_PER_BLOCK;  // 4096
    ball_query_kernel<<<blocks, BLOCK_THREADS>>>(xyz, out);
}

// round 6
// speedup vs baseline: 1.0303x; 1.0303x over previous
#include <cuda_runtime.h>
#include <cuda_bf16.h>

#define NSAMPLE 32
#define NPTS 4096
#define MAXB 8
#define BLOCK_THREADS 256
#define WARPS_PER_BLOCK (BLOCK_THREADS / 32)

// Packed points: (x, y, z, |p|^2). 8*4096*16B = 512KB, L2-resident scratch.
__device__ float4 g_pts[MAXB * NPTS];

// Pre-pass: pack xyz + squared norm. The |p|^2 expression is BIT-IDENTICAL to
// the round-5 passing kernel: rn((rn(x*x) + rn(y*y)) + rn(z*z)), no FMA.
__global__ void pack_kernel(const float* __restrict__ xyz, int total) {
    const int i = blockIdx.x * blockDim.x + threadIdx.x;
    if (i < total) {
        const float x = xyz[i * 3 + 0];
        const float y = xyz[i * 3 + 1];
        const float z = xyz[i * 3 + 2];
        const float sq = __fadd_rn(__fadd_rn(__fmul_rn(x, x), __fmul_rn(y, y)),
                                   __fmul_rn(z, z));
        g_pts[i] = make_float4(x, y, z, sq);
    }
}

// One warp per query point. Inner loop is now a single LDG.128 per lane per
// 32-point chunk (vs 3 strided LDG.32 + norm recompute). All floating-point
// expressions are bit-identical to the round-5 passing kernel; only the data
// layout changed. Ballot gives hits in ascending-index order; popc-prefix
// ranks write slots; warp-uniform break at 32 hits; pad with first hit.
__global__ void ball_query_kernel(float* __restrict__ out) {
    const int lane = threadIdx.x & 31;
    const int gw = blockIdx.x * WARPS_PER_BLOCK + (threadIdx.x >> 5);
    const int b = gw >> 12;          // / NPTS

    const float4* __restrict__ base = g_pts + (size_t)b * NPTS;

    const float4 q = g_pts[gw];      // query point (b*NPTS + m == gw)
    const float qx = q.x, qy = q.y, qz = q.z, qw = q.w;

    float* o = out + (size_t)gw * NSAMPLE;

    int count = 0;
    int first = -1;
    const float r2 = 0.04f;  // f32 promotion of 0.2*0.2, as jnp compares

    for (int nb = 0; nb < NPTS; nb += 32) {
        const float4 s = base[nb + lane];
        const float dot = __fadd_rn(__fadd_rn(__fmul_rn(qx, s.x), __fmul_rn(qy, s.y)),
                                    __fmul_rn(qz, s.z));
        // d2 = (|q|^2 + |p|^2) - 2*dot, exact round-5 expression order.
        const float d2 = __fadd_rn(__fadd_rn(qw, s.w), -__fmul_rn(2.0f, dot));

        const bool hit = d2 < r2;
        const unsigned bal = __ballot_sync(0xffffffffu, hit);
        if (bal) {
            if (first < 0) first = nb + (__ffs(bal) - 1);
            const int rank = __popc(bal & ((1u << lane) - 1u));
            if (hit) {
                const int slot = count + rank;
                if (slot < NSAMPLE) o[slot] = (float)(nb + lane);
            }
            count += __popc(bal);
            if (count >= NSAMPLE) break;  // count is warp-uniform
        }
    }

    if (count < NSAMPLE) {
        const int i = count + lane;
        if (i < NSAMPLE) o[i] = (float)first;
    }
}

extern "C" void kernel_launch(void* const* d_in, const int* in_sizes, int n_in,
                              void* d_out, int out_size) {
    const float* xyz = (const float*)d_in[0];  // 'xyz' (B, N, 3) float32
    // d_in[1] ('xyz_new') is unused by the reference (it queries xyz vs xyz).
    const int B = in_sizes[0] / (NPTS * 3);    // 8
    float* out = (float*)d_out;

    const int total = B * NPTS;  // 32768
    pack_kernel<<<(total + BLOCK_THREADS - 1) / BLOCK_THREADS, BLOCK_THREADS>>>(xyz, total);

    const int blocks = total / WARPS_PER_BLOCK;  // 4096
    ball_query_kernel<<<blocks, BLOCK_THREADS>>>(out);
}

// round 7
// speedup vs baseline: 1.3365x; 1.2972x over previous
#include <cuda_runtime.h>
#include <cuda_bf16.h>

#define NSAMPLE 32
#define NPTS 4096
#define MAXB 8
#define BLOCK_THREADS 128
#define WARPS_PER_BLOCK (BLOCK_THREADS / 32)

// Packed points: (x, y, z, |p|^2). 8*4096*16B = 512KB, L1/L2-resident scratch.
__device__ float4 g_pts[MAXB * NPTS];

// Pre-pass: pack xyz + squared norm. |p|^2 is BIT-IDENTICAL to the passing
// round-5/6 kernels: rn((rn(x*x) + rn(y*y)) + rn(z*z)), no FMA contraction.
__global__ void pack_kernel(const float* __restrict__ xyz, int total) {
    const int i = blockIdx.x * blockDim.x + threadIdx.x;
    if (i < total) {
        const float x = xyz[i * 3 + 0];
        const float y = xyz[i * 3 + 1];
        const float z = xyz[i * 3 + 2];
        const float sq = __fadd_rn(__fadd_rn(__fmul_rn(x, x), __fmul_rn(y, y)),
                                   __fmul_rn(z, z));
        g_pts[i] = make_float4(x, y, z, sq);
    }
}

// One warp per query point with DEPTH-1 SOFTWARE PREFETCH: the next chunk's
// LDG.128 issues before the current chunk's ballot/branch chain, overlapping
// load latency with compute on the (data-dependent-exit) loop that the
// compiler cannot pipeline itself. FP math bit-identical to round 5/6.
__global__ void ball_query_kernel(float* __restrict__ out) {
    const int lane = threadIdx.x & 31;
    const int gw = blockIdx.x * WARPS_PER_BLOCK + (threadIdx.x >> 5);
    const int b = gw >> 12;          // / NPTS

    const float4* __restrict__ base = g_pts + (size_t)b * NPTS;

    const float4 q = g_pts[gw];      // query point (gw == b*NPTS + m)
    const float qx = q.x, qy = q.y, qz = q.z, qw = q.w;

    float* o = out + (size_t)gw * NSAMPLE;

    int count = 0;
    int first = -1;
    const float r2 = 0.04f;  // f32 promotion of 0.2*0.2, as jnp compares

    float4 s = base[lane];   // prefetch chunk 0

    for (int nb = 0; nb < NPTS; nb += 32) {
        const float4 cur = s;
        // Prefetch next chunk NOW (clamped re-read of chunk 0 on the last
        // iteration — harmless). This LDG has no dependence on the ballot
        // chain below, so it issues immediately and hides its latency.
        const int np = (nb + 32 < NPTS) ? (nb + 32) : 0;
        s = base[np + lane];

        const float dot = __fadd_rn(__fadd_rn(__fmul_rn(qx, cur.x), __fmul_rn(qy, cur.y)),
                                    __fmul_rn(qz, cur.z));
        // d2 = (|q|^2 + |p|^2) - 2*dot, exact frozen expression order.
        const float d2 = __fadd_rn(__fadd_rn(qw, cur.w), -__fmul_rn(2.0f, dot));

        const bool hit = d2 < r2;
        const unsigned bal = __ballot_sync(0xffffffffu, hit);
        if (bal) {
            if (first < 0) first = nb + (__ffs(bal) - 1);
            const int rank = __popc(bal & ((1u << lane) - 1u));
            if (hit) {
                const int slot = count + rank;
                if (slot < NSAMPLE) o[slot] = (float)(nb + lane);
            }
            count += __popc(bal);
            if (count >= NSAMPLE) break;  // count is warp-uniform
        }
    }

    if (count < NSAMPLE) {
        const int i = count + lane;
        if (i < NSAMPLE) o[i] = (float)first;
    }
}

extern "C" void kernel_launch(void* const* d_in, const int* in_sizes, int n_in,
                              void* d_out, int out_size) {
    const float* xyz = (const float*)d_in[0];  // 'xyz' (B, N, 3) float32
    // d_in[1] ('xyz_new') is unused by the reference (it queries xyz vs xyz).
    const int B = in_sizes[0] / (NPTS * 3);    // 8
    float* out = (float*)d_out;

    const int total = B * NPTS;  // 32768
    pack_kernel<<<(total + 255) / 256, 256>>>(xyz, total);

    const int blocks = total / WARPS_PER_BLOCK;  // 8192
    ball_query_kernel<<<blocks, BLOCK_THREADS>>>(out);
}

// round 8
// speedup vs baseline: 1.5040x; 1.1253x over previous
#include <cuda_runtime.h>
#include <cuda_bf16.h>

#define NSAMPLE 32
#define NPTS 4096
#define MAXB 8
#define BLOCK_THREADS 64
#define WARPS_PER_BLOCK (BLOCK_THREADS / 32)

// Packed points: (x, y, z, |p|^2). 8*4096*16B = 512KB, L1/L2-resident scratch.
__device__ float4 g_pts[MAXB * NPTS];

// Pre-pass: pack xyz + squared norm. |p|^2 BIT-IDENTICAL to rounds 5-7:
// rn((rn(x*x) + rn(y*y)) + rn(z*z)), no FMA contraction.
__global__ void pack_kernel(const float* __restrict__ xyz, int total) {
    const int i = blockIdx.x * blockDim.x + threadIdx.x;
    if (i < total) {
        const float x = xyz[i * 3 + 0];
        const float y = xyz[i * 3 + 1];
        const float z = xyz[i * 3 + 2];
        const float sq = __fadd_rn(__fadd_rn(__fmul_rn(x, x), __fmul_rn(y, y)),
                                   __fmul_rn(z, z));
        g_pts[i] = make_float4(x, y, z, sq);
    }
}

// One warp per query. 64 points per iteration with depth-2 register prefetch:
// loop control, prefetch address math and the break check amortize over 2
// chunks, and the two independent LDG.128->dot chains overlap. Ballot0 is
// consumed fully before ballot1, preserving ascending-index emission. All FP
// expressions are bit-identical to the passing rounds 5-7.
__global__ void ball_query_kernel(float* __restrict__ out) {
    const int lane = threadIdx.x & 31;
    const int gw = blockIdx.x * WARPS_PER_BLOCK + (threadIdx.x >> 5);
    const int b = gw >> 12;          // / NPTS

    const float4* __restrict__ base = g_pts + (size_t)b * NPTS;

    const float4 q = g_pts[gw];      // query point (gw == b*NPTS + m)
    const float qx = q.x, qy = q.y, qz = q.z, qw = q.w;

    float* o = out + (size_t)gw * NSAMPLE;

    int count = 0;
    int first = -1;
    const float r2 = 0.04f;  // f32 promotion of 0.2*0.2, as jnp compares

    float4 s0 = base[lane];          // prefetch chunk 0
    float4 s1 = base[32 + lane];     // prefetch chunk 1

    for (int nb = 0; nb < NPTS; nb += 64) {
        const float4 c0 = s0;
        const float4 c1 = s1;
        // Prefetch the next pair now (wraps to 0 on the last iteration —
        // harmless re-read). Independent of the ballot chain below.
        const int np = (nb + 64) & (NPTS - 1);
        s0 = base[np + lane];
        s1 = base[np + 32 + lane];

        const float dot0 = __fadd_rn(__fadd_rn(__fmul_rn(qx, c0.x), __fmul_rn(qy, c0.y)),
                                     __fmul_rn(qz, c0.z));
        const float d20 = __fadd_rn(__fadd_rn(qw, c0.w), -__fmul_rn(2.0f, dot0));
        const float dot1 = __fadd_rn(__fadd_rn(__fmul_rn(qx, c1.x), __fmul_rn(qy, c1.y)),
                                     __fmul_rn(qz, c1.z));
        const float d21 = __fadd_rn(__fadd_rn(qw, c1.w), -__fmul_rn(2.0f, dot1));

        const unsigned bal0 = __ballot_sync(0xffffffffu, d20 < r2);
        const unsigned bal1 = __ballot_sync(0xffffffffu, d21 < r2);

        if (bal0 | bal1) {
            if (first < 0) {
                first = bal0 ? nb + (__ffs(bal0) - 1)
                             : nb + 32 + (__ffs(bal1) - 1);
            }
            const unsigned mlt = (1u << lane) - 1u;  // lanes below me
            if (d20 < r2) {
                const int slot = count + __popc(bal0 & mlt);
                if (slot < NSAMPLE) o[slot] = (float)(nb + lane);
            }
            count += __popc(bal0);
            if (d21 < r2) {
                const int slot = count + __popc(bal1 & mlt);
                if (slot < NSAMPLE) o[slot] = (float)(nb + 32 + lane);
            }
            count += __popc(bal1);
            if (count >= NSAMPLE) break;  // count is warp-uniform
        }
    }

    if (count < NSAMPLE) {
        const int i = count + lane;
        if (i < NSAMPLE) o[i] = (float)first;
    }
}

extern "C" void kernel_launch(void* const* d_in, const int* in_sizes, int n_in,
                              void* d_out, int out_size) {
    const float* xyz = (const float*)d_in[0];  // 'xyz' (B, N, 3) float32
    // d_in[1] ('xyz_new') is unused by the reference (it queries xyz vs xyz).
    const int B = in_sizes[0] / (NPTS * 3);    // 8
    float* out = (float*)d_out;

    const int total = B * NPTS;  // 32768
    pack_kernel<<<(total + 255) / 256, 256>>>(xyz, total);

    const int blocks = total / WARPS_PER_BLOCK;  // 16384
    ball_query_kernel<<<blocks, BLOCK_THREADS>>>(out);
}

// round 9
// speedup vs baseline: 1.5234x; 1.0129x over previous
#include <cuda_runtime.h>
#include <cuda_bf16.h>

#define NSAMPLE 32
#define NPTS 4096
#define MAXB 8
#define BLOCK_THREADS 64
#define WARPS_PER_BLOCK (BLOCK_THREADS / 32)
#define SCR_STRIDE 128   // padded per-query scratch row (max overshoot 94)

// Packed points: (x, y, z, |p|^2). 512KB, L1/L2-resident.
__device__ float4 g_pts[MAXB * NPTS];
// Deferred-emission scratch: hits written unguarded, 128 slots/query (16MB).
__device__ float g_scr[MAXB * NPTS * SCR_STRIDE];

// Pre-pass: pack xyz + squared norm. |p|^2 BIT-IDENTICAL to rounds 5-8:
// rn((rn(x*x) + rn(y*y)) + rn(z*z)), no FMA contraction.
__global__ void pack_kernel(const float* __restrict__ xyz, int total) {
    const int i = blockIdx.x * blockDim.x + threadIdx.x;
    if (i < total) {
        const float x = xyz[i * 3 + 0];
        const float y = xyz[i * 3 + 1];
        const float z = xyz[i * 3 + 2];
        const float sq = __fadd_rn(__fadd_rn(__fmul_rn(x, x), __fmul_rn(y, y)),
                                   __fmul_rn(z, z));
        g_pts[i] = make_float4(x, y, z, sq);
    }
}

// One warp per query, 64 points/iter, depth-2 register prefetch. Emission is
// DEFERRED: hits go unguarded into a padded scratch row (ballot rank -> slot,
// ascending order preserved), the loop has no slot guard, no first-tracking,
// no hit branch — only the warp-uniform break. Epilogue: lane i emits
// scr[i < count ? i : 0], which is simultaneously the copy, the 32-slot
// truncation, and the pad-with-first (scr[0] == smallest hit; self-hit
// guarantees count >= 1). FP math bit-identical to passing rounds 5-8.
__global__ void ball_query_kernel(float* __restrict__ out) {
    const int lane = threadIdx.x & 31;
    const int gw = blockIdx.x * WARPS_PER_BLOCK + (threadIdx.x >> 5);
    const int b = gw >> 12;          // / NPTS

    const float4* __restrict__ base = g_pts + (size_t)b * NPTS;
    float* __restrict__ scr = g_scr + (size_t)gw * SCR_STRIDE;

    const float4 q = g_pts[gw];      // query point (gw == b*NPTS + m)
    const float qx = q.x, qy = q.y, qz = q.z, qw = q.w;

    const unsigned mlt = (1u << lane) - 1u;
    const float r2 = 0.04f;          // f32 promotion of 0.2*0.2
    int count = 0;

    float4 s0 = base[lane];          // prefetch chunk 0
    float4 s1 = base[32 + lane];     // prefetch chunk 1

    for (int nb = 0; nb < NPTS; nb += 64) {
        const float4 c0 = s0;
        const float4 c1 = s1;
        const int np = (nb + 64) & (NPTS - 1);   // wrap: harmless re-read
        s0 = base[np + lane];
        s1 = base[np + 32 + lane];

        const float dot0 = __fadd_rn(__fadd_rn(__fmul_rn(qx, c0.x), __fmul_rn(qy, c0.y)),
                                     __fmul_rn(qz, c0.z));
        const float d20 = __fadd_rn(__fadd_rn(qw, c0.w), -__fmul_rn(2.0f, dot0));
        const float dot1 = __fadd_rn(__fadd_rn(__fmul_rn(qx, c1.x), __fmul_rn(qy, c1.y)),
                                     __fmul_rn(qz, c1.z));
        const float d21 = __fadd_rn(__fadd_rn(qw, c1.w), -__fmul_rn(2.0f, dot1));

        const bool h0 = d20 < r2;
        const bool h1 = d21 < r2;
        const unsigned bal0 = __ballot_sync(0xffffffffu, h0);
        const unsigned bal1 = __ballot_sync(0xffffffffu, h1);

        if (h0) scr[count + __popc(bal0 & mlt)] = (float)(nb + lane);
        const int c0n = count + __popc(bal0);
        if (h1) scr[c0n + __popc(bal1 & mlt)] = (float)(nb + 32 + lane);
        count = c0n + __popc(bal1);

        if (count >= NSAMPLE) break;  // count is warp-uniform
    }

    __syncwarp();                     // fences scratch writes within the warp
    const int sel = (lane < count) ? lane : 0;
    out[(size_t)gw * NSAMPLE + lane] = scr[sel];
}

extern "C" void kernel_launch(void* const* d_in, const int* in_sizes, int n_in,
                              void* d_out, int out_size) {
    const float* xyz = (const float*)d_in[0];  // 'xyz' (B, N, 3) float32
    // d_in[1] ('xyz_new') is unused by the reference (it queries xyz vs xyz).
    const int B = in_sizes[0] / (NPTS * 3);    // 8
    float* out = (float*)d_out;

    const int total = B * NPTS;  // 32768
    pack_kernel<<<(total + 255) / 256, 256>>>(xyz, total);

    const int blocks = total / WARPS_PER_BLOCK;  // 16384
    ball_query_kernel<<<blocks, BLOCK_THREADS>>>(out);
}

// round 10
// speedup vs baseline: 1.5583x; 1.0229x over previous
#include <cuda_runtime.h>
#include <cuda_bf16.h>

#define NSAMPLE 32
#define NPTS 4096
#define MAXB 8
#define BLOCK_THREADS 64
#define WARPS_PER_BLOCK (BLOCK_THREADS / 32)
#define SCR_SLOTS 128   // per-warp scratch (max slot overshoot 94)

// Packed points: (x, y, z, |p|^2), +64 pad so the depth-2 pointer prefetch may
// harmlessly overrun on the final iteration (values loaded, never consumed).
__device__ float4 g_pts[MAXB * NPTS + 64];

// ---- f32x2 packed helpers (sm_103a): two independent IEEE rn f32 ops per
// instruction; each half is bit-identical to the scalar __fmul_rn/__fadd_rn.
__device__ __forceinline__ unsigned long long pk2(float lo, float hi) {
    unsigned long long r;
    asm("mov.b64 %0, {%1, %2};" : "=l"(r) : "f"(lo), "f"(hi));
    return r;
}
__device__ __forceinline__ void upk2(unsigned long long v, float& lo, float& hi) {
    asm("mov.b64 {%0, %1}, %2;" : "=f"(lo), "=f"(hi) : "l"(v));
}
__device__ __forceinline__ unsigned long long mul2(unsigned long long a,
                                                   unsigned long long b) {
    unsigned long long r;
    asm("mul.rn.f32x2 %0, %1, %2;" : "=l"(r) : "l"(a), "l"(b));
    return r;
}
__device__ __forceinline__ unsigned long long add2(unsigned long long a,
                                                   unsigned long long b) {
    unsigned long long r;
    asm("add.rn.f32x2 %0, %1, %2;" : "=l"(r) : "l"(a), "l"(b));
    return r;
}

// Pre-pass: pack xyz + squared norm. |p|^2 BIT-IDENTICAL to rounds 5-9:
// rn((rn(x*x) + rn(y*y)) + rn(z*z)), no FMA contraction.
__global__ void pack_kernel(const float* __restrict__ xyz, int total) {
    const int i = blockIdx.x * blockDim.x + threadIdx.x;
    if (i < total) {
        const float x = xyz[i * 3 + 0];
        const float y = xyz[i * 3 + 1];
        const float z = xyz[i * 3 + 2];
        const float sq = __fadd_rn(__fadd_rn(__fmul_rn(x, x), __fmul_rn(y, y)),
                                   __fmul_rn(z, z));
        g_pts[i] = make_float4(x, y, z, sq);
    }
}

// One warp per query, 64 points/iter, depth-2 pointer prefetch, f32x2 packed
// distance math (both chunks per instruction), shared-memory deferred
// emission. Per-half results are bit-identical to the passing rounds 5-9:
//   dot = rn(rn(rn(qx*px)+rn(qy*py)) + rn(qz*pz))
//   d2  = rn(rn(qw+pw) + rn(-2*dot))      [rn(-2*dot) == -rn(2*dot), exact]
__global__ void ball_query_kernel(float* __restrict__ out) {
    __shared__ float scr[WARPS_PER_BLOCK][SCR_SLOTS];

    const int lane = threadIdx.x & 31;
    const int w = threadIdx.x >> 5;
    const int gw = blockIdx.x * WARPS_PER_BLOCK + w;
    const int b = gw >> 12;          // / NPTS

    const float4* __restrict__ p = g_pts + (size_t)b * NPTS;

    const float4 q = g_pts[gw];      // query point (gw == b*NPTS + m)
    const unsigned long long qxp = pk2(q.x, q.x);
    const unsigned long long qyp = pk2(q.y, q.y);
    const unsigned long long qzp = pk2(q.z, q.z);
    const unsigned long long qwp = pk2(q.w, q.w);
    const unsigned long long M2  = pk2(-2.0f, -2.0f);

    const unsigned mlt = (1u << lane) - 1u;
    const float r2 = 0.04f;          // f32 promotion of 0.2*0.2
    int count = 0;

    float4 s0 = p[lane];             // prefetch chunk 0
    float4 s1 = p[32 + lane];        // prefetch chunk 1
    p += 64;

    float f0 = (float)lane;          // emission values, advanced by 64.0f/iter
    float f1 = (float)(lane + 32);

    for (int nb = 0; nb < NPTS; nb += 64) {
        const float4 c0 = s0;
        const float4 c1 = s1;
        s0 = p[lane];                // final-iter overrun lands in the pad
        s1 = p[32 + lane];
        p += 64;

        const unsigned long long px = pk2(c0.x, c1.x);
        const unsigned long long py = pk2(c0.y, c1.y);
        const unsigned long long pz = pk2(c0.z, c1.z);
        const unsigned long long pw = pk2(c0.w, c1.w);

        const unsigned long long dot =
            add2(add2(mul2(qxp, px), mul2(qyp, py)), mul2(qzp, pz));
        const unsigned long long d2p = add2(add2(qwp, pw), mul2(dot, M2));

        float d20, d21;
        upk2(d2p, d20, d21);

        const bool h0 = d20 < r2;
        const bool h1 = d21 < r2;
        const unsigned bal0 = __ballot_sync(0xffffffffu, h0);
        const unsigned bal1 = __ballot_sync(0xffffffffu, h1);

        if (h0) scr[w][count + __popc(bal0 & mlt)] = f0;
        const int cn = count + __popc(bal0);
        if (h1) scr[w][cn + __popc(bal1 & mlt)] = f1;
        count = cn + __popc(bal1);

        f0 += 64.0f;
        f1 += 64.0f;

        if (count >= NSAMPLE) break;  // count is warp-uniform
    }

    __syncwarp();                     // order scratch stores within the warp
    const int sel = (lane < count) ? lane : 0;  // scr[0] == smallest hit
    out[(size_t)gw * NSAMPLE + lane] = scr[w][sel];
}

extern "C" void kernel_launch(void* const* d_in, const int* in_sizes, int n_in,
                              void* d_out, int out_size) {
    const float* xyz = (const float*)d_in[0];  // 'xyz' (B, N, 3) float32
    // d_in[1] ('xyz_new') is unused by the reference (it queries xyz vs xyz).
    const int B = in_sizes[0] / (NPTS * 3);    // 8
    float* out = (float*)d_out;

    const int total = B * NPTS;  // 32768
    pack_kernel<<<(total + 255) / 256, 256>>>(xyz, total);

    const int blocks = total / WARPS_PER_BLOCK;  // 16384
    ball_query_kernel<<<blocks, BLOCK_THREADS>>>(out);
}